// round 2
// baseline (speedup 1.0000x reference)
#include <cuda_runtime.h>
#include <math_constants.h>

#define NBINS 512
#define KNN   16
#define BATCH 8192
#define NROWS 100000
#define CSB   64          // colsum blocks

// Scratch (allocation-free rule: __device__ globals). No zeroing needed:
// every element is unconditionally written each call.
__device__ float g_part[CSB][NBINS];   // per-block column partial sums
__device__ float g_bsum[BATCH];        // per-batch-row  sum(add)*weight

// Column partial sums of outputs[0:BATCH, :]. Block g handles 128 rows.
__global__ void colsum_kernel(const float* __restrict__ outputs) {
    int col = threadIdx.x;
    int r0  = blockIdx.x * (BATCH / CSB);
    float acc = 0.0f;
#pragma unroll 8
    for (int r = 0; r < BATCH / CSB; r++)
        acc += outputs[(size_t)(r0 + r) * NBINS + col];
    g_part[blockIdx.x][col] = acc;
}

// One block per batch row b. Base row cached in SMEM; warp w computes
// add[b,w] = max_j (outputs[nns[b,w], j] + outputs[b, j]).
__global__ __launch_bounds__(512, 4)
void main_kernel(const float* __restrict__ outputs,
                 const float* __restrict__ y,
                 const float* __restrict__ weights,
                 float* __restrict__ booster) {
    __shared__ __align__(16) float base[NBINS];
    __shared__ float s_add[KNN];

    int b    = blockIdx.x;
    int tid  = threadIdx.x;
    int warp = tid >> 5;
    int lane = tid & 31;

    base[tid] = outputs[(size_t)b * NBINS + tid];
    __syncthreads();

    int idx = (int)y[b * KNN + warp];   // trunc; y >= 0
    const float4* g4 = (const float4*)(outputs + (size_t)idx * NBINS);
    const float4* b4 = (const float4*)base;

    float m = -CUDART_INF_F;
#pragma unroll
    for (int t = 0; t < 4; t++) {
        float4 a = g4[t * 32 + lane];
        float4 c = b4[t * 32 + lane];
        m = fmaxf(m, fmaxf(fmaxf(a.x + c.x, a.y + c.y),
                           fmaxf(a.z + c.z, a.w + c.w)));
    }
#pragma unroll
    for (int o = 16; o; o >>= 1)
        m = fmaxf(m, __shfl_xor_sync(0xFFFFFFFFu, m, o));
    if (lane == 0) s_add[warp] = m;
    __syncthreads();

    if (tid == 0) {
        float s = 0.0f;
#pragma unroll
        for (int k = 0; k < KNN; k++) s += s_add[k];
        booster[b] = fmaxf(0.5f, (2.0f - s * (1.0f / KNN)) * 0.5f);
        g_bsum[b]  = s * weights[b];
    }
}

// Single block, 512 threads, 2 barriers total.
__global__ void final_kernel(float* __restrict__ out) {
    __shared__ float  smx[16], smn[16];
    __shared__ double ssum[16];
    int t    = threadIdx.x;
    int warp = t >> 5;
    int lane = t & 31;

    // Column sums: thread t owns column t.
    float v = 0.0f;
#pragma unroll
    for (int i = 0; i < CSB; i++) v += g_part[i][t];
    float mx = v, mn = v;
#pragma unroll
    for (int o = 16; o; o >>= 1) {
        mx = fmaxf(mx, __shfl_xor_sync(0xFFFFFFFFu, mx, o));
        mn = fminf(mn, __shfl_xor_sync(0xFFFFFFFFu, mn, o));
    }

    // Weighted add-sum: thread t owns 16 strided elements of g_bsum.
    double ds = 0.0;
#pragma unroll
    for (int i = 0; i < BATCH / 512; i++)
        ds += (double)g_bsum[t + i * 512];
#pragma unroll
    for (int o = 16; o; o >>= 1)
        ds += __shfl_xor_sync(0xFFFFFFFFu, ds, o);

    if (lane == 0) { smx[warp] = mx; smn[warp] = mn; ssum[warp] = ds; }
    __syncthreads();

    if (warp == 0) {
        mx = smx[lane & 15];
        mn = smn[lane & 15];
        ds = ssum[lane & 15];
#pragma unroll
        for (int o = 8; o; o >>= 1) {
            mx = fmaxf(mx, __shfl_xor_sync(0xFFFFFFFFu, mx, o));
            mn = fminf(mn, __shfl_xor_sync(0xFFFFFFFFu, mn, o));
            ds += __shfl_xor_sync(0xFFFFFFFFu, ds, o);
        }
        if (lane == 0) {
            float bb       = mx - mn;
            float target_b = (float)NROWS / (float)NBINS;
            float ratio    = bb / target_b;
            float add_mean = (float)(ds / (double)(BATCH * KNN));
            float d        = 2.0f - add_mean;
            d = d * d;
            out[0] = ratio + d;  // cost
            out[1] = d;          // diff
            out[2] = ratio;      // b / target_b
        }
    }
}

extern "C" void kernel_launch(void* const* d_in, const int* in_sizes, int n_in,
                              void* d_out, int out_size) {
    const float* outputs = (const float*)d_in[0];
    const float* y       = (const float*)d_in[1];
    const float* weights = (const float*)d_in[2];
    float* out = (float*)d_out;

    colsum_kernel<<<CSB, NBINS>>>(outputs);
    main_kernel<<<BATCH, NBINS>>>(outputs, y, weights, out + 3);
    final_kernel<<<1, NBINS>>>(out);
}